// round 11
// baseline (speedup 1.0000x reference)
#include <cuda_runtime.h>
#include <math.h>
#include <stdint.h>

#define Hdim   1024
#define Edim   512
#define GATES  4096          // 4*Hdim
#define MAXS   2048
#define MAXD   512
#define G_CTAS 128           // Hdim/8 CTAs, all resident (<=148 SMs)
#define POISON 0x7FBFFFFFu   // NaN bit pattern; h=o*tanh(c) can never be NaN

// ---------------- persistent device state ----------------
__device__ __align__(16) float d_Xp[(size_t)MAXS * GATES];               // encoder input projections (+bias)
__device__ __align__(16) float d_Hbuf[(size_t)(MAXS + MAXD + 1) * Hdim]; // h_t for every step (step-indexed)

// ---------------- init: zero h0, poison h1..hTS (data-is-the-flag sync) ----------------
__global__ void init_kernel(int total_steps) {
    size_t i = (size_t)blockIdx.x * blockDim.x + threadIdx.x;
    size_t tot = (size_t)(total_steps + 1) * Hdim;
    if (i < Hdim) d_Hbuf[i] = 0.0f;
    else if (i < tot) ((uint32_t*)d_Hbuf)[i] = POISON;
}

// ---------------- tf32 helpers ----------------
__device__ __forceinline__ uint32_t f2tf32(float x) {
    uint32_t u;
    asm("cvt.rna.tf32.f32 %0, %1;" : "=r"(u) : "f"(x));
    return u;
}

__device__ __forceinline__ void mma_tf32(float d[4], const uint32_t a[4],
                                         const uint32_t b[2]) {
    asm volatile("mma.sync.aligned.m16n8k8.row.col.f32.tf32.tf32.f32 "
                 "{%0,%1,%2,%3}, {%4,%5,%6,%7}, {%8,%9}, {%0,%1,%2,%3};"
                 : "+f"(d[0]), "+f"(d[1]), "+f"(d[2]), "+f"(d[3])
                 : "r"(a[0]), "r"(a[1]), "r"(a[2]), "r"(a[3]),
                   "r"(b[0]), "r"(b[1]));
}

#define OG_STR 36

// ---------------- Xp GEMM (tf32): Xp[t][r] = Wih[r,:].emb[state[t],:] + b[r] ----------------
__global__ __launch_bounds__(256, 2) void xp_gemm_tc(const int* __restrict__ state,
                                                     const float* __restrict__ Wih,
                                                     const float* __restrict__ emb,
                                                     const float* __restrict__ bih,
                                                     const float* __restrict__ bhh,
                                                     int S) {
    __shared__ uint32_t As[128 * OG_STR];
    __shared__ uint32_t Bs[128 * OG_STR];

    int bn = blockIdx.x, bm = blockIdx.y;
    int tid = threadIdx.x;
    int warp = tid >> 5;
    int lane = tid & 31;
    int grp = lane >> 2;
    int tg  = lane & 3;
    int wm = (warp & 1) * 64;
    int wn = (warp >> 1) * 32;

    int lr = tid >> 1;
    int part = (tid & 1) * 16;

    const float* Aptr = Wih + (size_t)(bm * 128 + lr) * Edim + part;
    int nrow = bn * 128 + lr; if (nrow >= S) nrow = S - 1;
    const float* Bptr = emb + (size_t)state[nrow] * Edim + part;

    float d[4][4][4];
#pragma unroll
    for (int i = 0; i < 4; i++)
#pragma unroll
        for (int j = 0; j < 4; j++)
#pragma unroll
            for (int k = 0; k < 4; k++) d[i][j][k] = 0.0f;

    for (int k0 = 0; k0 < Edim; k0 += 32) {
#pragma unroll
        for (int i = 0; i < 4; i++) {
            float4 av = *(const float4*)(Aptr + k0 + i * 4);
            float4 bv = *(const float4*)(Bptr + k0 + i * 4);
            uint32_t* ad = &As[lr * OG_STR + part + i * 4];
            uint32_t* bd = &Bs[lr * OG_STR + part + i * 4];
            ad[0] = f2tf32(av.x); ad[1] = f2tf32(av.y);
            ad[2] = f2tf32(av.z); ad[3] = f2tf32(av.w);
            bd[0] = f2tf32(bv.x); bd[1] = f2tf32(bv.y);
            bd[2] = f2tf32(bv.z); bd[3] = f2tf32(bv.w);
        }
        __syncthreads();

#pragma unroll
        for (int kk = 0; kk < 32; kk += 8) {
            uint32_t fb[4][2];
#pragma unroll
            for (int na = 0; na < 4; na++) {
                int n = wn + na * 8 + grp;
                fb[na][0] = Bs[n * OG_STR + kk + tg];
                fb[na][1] = Bs[n * OG_STR + kk + tg + 4];
            }
            uint32_t fa[4][4];
#pragma unroll
            for (int ma = 0; ma < 4; ma++) {
                int m = wm + ma * 16;
                fa[ma][0] = As[(m + grp) * OG_STR + kk + tg];
                fa[ma][1] = As[(m + 8 + grp) * OG_STR + kk + tg];
                fa[ma][2] = As[(m + grp) * OG_STR + kk + tg + 4];
                fa[ma][3] = As[(m + 8 + grp) * OG_STR + kk + tg + 4];
            }
#pragma unroll
            for (int ma = 0; ma < 4; ma++)
#pragma unroll
                for (int na = 0; na < 4; na++)
                    mma_tf32(d[ma][na], fa[ma], fb[na]);
        }
        __syncthreads();
    }

    // transposed epilogue: Xp[t][r] = d + bias[r]
#pragma unroll
    for (int ma = 0; ma < 4; ma++) {
        int m0 = bm * 128 + wm + ma * 16 + grp;
        float b0 = bih[m0] + bhh[m0];
        float b1 = bih[m0 + 8] + bhh[m0 + 8];
#pragma unroll
        for (int na = 0; na < 4; na++) {
            int n0 = bn * 128 + wn + na * 8 + tg * 2;
            if (n0 < S) {
                float* xr = d_Xp + (size_t)n0 * GATES;
                xr[m0]     = d[ma][na][0] + b0;
                xr[m0 + 8] = d[ma][na][2] + b1;
            }
            if (n0 + 1 < S) {
                float* xr = d_Xp + (size_t)(n0 + 1) * GATES;
                xr[m0]     = d[ma][na][1] + b0;
                xr[m0 + 8] = d[ma][na][3] + b1;
            }
        }
    }
}

// ---------------- persistent recurrence kernel ----------------
__device__ __forceinline__ float sigmoid_f(float x) { return 1.0f / (1.0f + __expf(-x)); }
__device__ __forceinline__ float tanh_f(float x) { return 1.0f - 2.0f / (__expf(2.0f * x) + 1.0f); }

__global__ __launch_bounds__(256, 1) void recur(const float* __restrict__ encWhh,
                                                const float* __restrict__ decWhh,
                                                const float* __restrict__ dbih,
                                                const float* __restrict__ dbhh,
                                                int S, int D) {
    __shared__ float4 hs4[8 * 33];   // padded h (33 float4 per 32-float4 segment)
    __shared__ float  g_s[32];
    __shared__ float  c_s[8];

    int tid = threadIdx.x;
    int b = blockIdx.x;
    int seg = tid & 7;
    int rl = tid >> 3;               // 0..31
    int gate = rl >> 3, q = rl & 7;
    int R = gate * 1024 + b * 8 + q;

    if (tid < 8) c_s[tid] = 0.0f;

    float4 w[32];
    {
        const float4* src = (const float4*)(encWhh + (size_t)R * Hdim + seg * 128);
#pragma unroll
        for (int k = 0; k < 32; k++) w[k] = src[k];
    }
    float decB = 0.0f;
    if (seg == 0) decB = dbih[R] + dbhh[R];

    int TS = S + D;
    for (int t = 0; t < TS; t++) {
        if (t == S) {  // switch to decoder weights
            const float4* src = (const float4*)(decWhh + (size_t)R * Hdim + seg * 128);
#pragma unroll
            for (int k = 0; k < 32; k++) w[k] = src[k];
        }

        // issue per-row additive term load EARLY (DRAM latency overlaps the poll)
        float extra = 0.0f;
        if (seg == 0) extra = (t < S) ? d_Xp[(size_t)t * GATES + R] : decB;

        // data-is-the-flag, LOW-CONTENTION: only 64 threads poll (64B each,
        // 4 independent v4 loads) -> 4x less L2 poll traffic; producers'
        // h-stores see far less interference on the polled lines.
        if (tid < 64) {
            const uint32_t* hp = (const uint32_t*)(d_Hbuf + (size_t)t * Hdim) + tid * 16;
            uint32_t v[16];
            bool ok;
            do {
                asm volatile("ld.relaxed.gpu.global.v4.u32 {%0,%1,%2,%3}, [%4];"
                             : "=r"(v[0]), "=r"(v[1]), "=r"(v[2]), "=r"(v[3]) : "l"(hp));
                asm volatile("ld.relaxed.gpu.global.v4.u32 {%0,%1,%2,%3}, [%4];"
                             : "=r"(v[4]), "=r"(v[5]), "=r"(v[6]), "=r"(v[7]) : "l"(hp + 4));
                asm volatile("ld.relaxed.gpu.global.v4.u32 {%0,%1,%2,%3}, [%4];"
                             : "=r"(v[8]), "=r"(v[9]), "=r"(v[10]), "=r"(v[11]) : "l"(hp + 8));
                asm volatile("ld.relaxed.gpu.global.v4.u32 {%0,%1,%2,%3}, [%4];"
                             : "=r"(v[12]), "=r"(v[13]), "=r"(v[14]), "=r"(v[15]) : "l"(hp + 12));
                ok = true;
#pragma unroll
                for (int j = 0; j < 16; j++) ok &= (v[j] != POISON);
            } while (!ok);
#pragma unroll
            for (int j = 0; j < 4; j++) {
                int g = tid * 4 + j;           // granule index 0..255
                float4 hv;
                hv.x = __uint_as_float(v[j * 4 + 0]);
                hv.y = __uint_as_float(v[j * 4 + 1]);
                hv.z = __uint_as_float(v[j * 4 + 2]);
                hv.w = __uint_as_float(v[j * 4 + 3]);
                hs4[g + (g >> 5)] = hv;
            }
        }
        __syncthreads();

        // 128-wide partial dot from register weights (4 independent chains)
        float a0 = 0, a1 = 0, a2 = 0, a3 = 0;
#pragma unroll
        for (int k = 0; k < 32; k += 2) {
            float4 h0 = hs4[seg * 33 + k];
            float4 h1 = hs4[seg * 33 + k + 1];
            a0 += w[k].x * h0.x;  a1 += w[k].y * h0.y;
            a2 += w[k].z * h0.z;  a3 += w[k].w * h0.w;
            a0 += w[k + 1].x * h1.x;  a1 += w[k + 1].y * h1.y;
            a2 += w[k + 1].z * h1.z;  a3 += w[k + 1].w * h1.w;
        }
        float acc = (a0 + a1) + (a2 + a3);
        acc += __shfl_xor_sync(0xffffffffu, acc, 1);
        acc += __shfl_xor_sync(0xffffffffu, acc, 2);
        acc += __shfl_xor_sync(0xffffffffu, acc, 4);
        if (seg == 0) g_s[rl] = acc + extra;
        __syncthreads();

        // LSTM cell: 32 lanes compute 4 gate activations in parallel, 8 finish
        if (tid < 32) {
            float gv = g_s[tid];
            float act = ((tid >> 3) == 2) ? tanh_f(gv) : sigmoid_f(gv);
            int qq = tid & 7;
            float a_i = __shfl_sync(0xffffffffu, act, qq);
            float a_f = __shfl_sync(0xffffffffu, act, 8 + qq);
            float a_g = __shfl_sync(0xffffffffu, act, 16 + qq);
            float a_o = __shfl_sync(0xffffffffu, act, 24 + qq);
            if (tid < 8) {
                float c = a_f * c_s[tid] + a_i * a_g;
                c_s[tid] = c;
                float h = a_o * tanh_f(c);
                float* hw = d_Hbuf + (size_t)(t + 1) * Hdim + b * 8 + tid;
                asm volatile("st.relaxed.gpu.global.f32 [%0], %1;"
                             :: "l"(hw), "f"(h) : "memory");
            }
        }
        // no global counter, no fence: next iteration's poll is the sync
    }
}

// ---------------- output GEMM (tf32 tensor cores) ----------------
__global__ __launch_bounds__(256, 2) void out_gemm_tc(const float* __restrict__ Wout,
                                                      const float* __restrict__ bout,
                                                      float* __restrict__ out,
                                                      int hoff, int M, int N) {
    __shared__ uint32_t As[128 * OG_STR];
    __shared__ uint32_t Bs[128 * OG_STR];

    int bn = blockIdx.x, bm = blockIdx.y;
    int tid = threadIdx.x;
    int warp = tid >> 5;
    int lane = tid & 31;
    int grp = lane >> 2;
    int tg  = lane & 3;
    int wm = (warp & 1) * 64;
    int wn = (warp >> 1) * 32;

    int lr = tid >> 1;
    int part = (tid & 1) * 16;

    const float* Aptr = d_Hbuf + (size_t)(hoff + bm * 128 + lr) * Hdim + part;
    int nrow = bn * 128 + lr; if (nrow >= N) nrow = N - 1;
    const float* Bptr = Wout + (size_t)nrow * Hdim + part;

    float d[4][4][4];
#pragma unroll
    for (int i = 0; i < 4; i++)
#pragma unroll
        for (int j = 0; j < 4; j++)
#pragma unroll
            for (int k = 0; k < 4; k++) d[i][j][k] = 0.0f;

    for (int k0 = 0; k0 < Hdim; k0 += 32) {
#pragma unroll
        for (int i = 0; i < 4; i++) {
            float4 av = *(const float4*)(Aptr + k0 + i * 4);
            float4 bv = *(const float4*)(Bptr + k0 + i * 4);
            uint32_t* ad = &As[lr * OG_STR + part + i * 4];
            uint32_t* bd = &Bs[lr * OG_STR + part + i * 4];
            ad[0] = f2tf32(av.x); ad[1] = f2tf32(av.y);
            ad[2] = f2tf32(av.z); ad[3] = f2tf32(av.w);
            bd[0] = f2tf32(bv.x); bd[1] = f2tf32(bv.y);
            bd[2] = f2tf32(bv.z); bd[3] = f2tf32(bv.w);
        }
        __syncthreads();

#pragma unroll
        for (int kk = 0; kk < 32; kk += 8) {
            uint32_t fb[4][2];
#pragma unroll
            for (int na = 0; na < 4; na++) {
                int n = wn + na * 8 + grp;
                fb[na][0] = Bs[n * OG_STR + kk + tg];
                fb[na][1] = Bs[n * OG_STR + kk + tg + 4];
            }
            uint32_t fa[4][4];
#pragma unroll
            for (int ma = 0; ma < 4; ma++) {
                int m = wm + ma * 16;
                fa[ma][0] = As[(m + grp) * OG_STR + kk + tg];
                fa[ma][1] = As[(m + 8 + grp) * OG_STR + kk + tg];
                fa[ma][2] = As[(m + grp) * OG_STR + kk + tg + 4];
                fa[ma][3] = As[(m + 8 + grp) * OG_STR + kk + tg + 4];
            }
#pragma unroll
            for (int ma = 0; ma < 4; ma++)
#pragma unroll
                for (int na = 0; na < 4; na++)
                    mma_tf32(d[ma][na], fa[ma], fb[na]);
        }
        __syncthreads();
    }

    // epilogue: scalar stores (N odd -> rows only 4B aligned)
#pragma unroll
    for (int ma = 0; ma < 4; ma++) {
        int m0 = bm * 128 + wm + ma * 16 + grp;
        float* r0 = out + (size_t)m0 * N;
        float* r1 = out + (size_t)(m0 + 8) * N;
#pragma unroll
        for (int na = 0; na < 4; na++) {
            int n0 = bn * 128 + wn + na * 8 + tg * 2;
            if (n0 < N) {
                float bb = bout[n0];
                r0[n0] = d[ma][na][0] + bb;
                r1[n0] = d[ma][na][2] + bb;
            }
            if (n0 + 1 < N) {
                float bb = bout[n0 + 1];
                r0[n0 + 1] = d[ma][na][1] + bb;
                r1[n0 + 1] = d[ma][na][3] + bb;
            }
        }
    }
}

// ---------------- row softmax (in place) ----------------
__global__ void softmax_rows(float* __restrict__ out, int N) {
    int row = blockIdx.x;
    float* p = out + (size_t)row * N;
    int tid = threadIdx.x;
    __shared__ float red[256];

    float mx = -1e30f;
    for (int i = tid; i < N; i += 256) mx = fmaxf(mx, p[i]);
    red[tid] = mx; __syncthreads();
    for (int s = 128; s > 0; s >>= 1) {
        if (tid < s) red[tid] = fmaxf(red[tid], red[tid + s]);
        __syncthreads();
    }
    mx = red[0]; __syncthreads();

    float sum = 0.0f;
    for (int i = tid; i < N; i += 256) sum += __expf(p[i] - mx);
    red[tid] = sum; __syncthreads();
    for (int s = 128; s > 0; s >>= 1) {
        if (tid < s) red[tid] += red[tid + s];
        __syncthreads();
    }
    float inv = 1.0f / red[0];

    for (int i = tid; i < N; i += 256) p[i] = __expf(p[i] - mx) * inv;
}

// ---------------- launch ----------------
extern "C" void kernel_launch(void* const* d_in, const int* in_sizes, int n_in,
                              void* d_out, int out_size) {
    const int*   state   = (const int*)d_in[0];
    const float* emb     = (const float*)d_in[2];
    const float* enc_Wih = (const float*)d_in[3];
    const float* enc_Whh = (const float*)d_in[4];
    const float* enc_bih = (const float*)d_in[5];
    const float* enc_bhh = (const float*)d_in[6];
    const float* dec_Whh = (const float*)d_in[8];
    const float* dec_bih = (const float*)d_in[9];
    const float* dec_bhh = (const float*)d_in[10];
    const float* Wout    = (const float*)d_in[11];
    const float* bout    = (const float*)d_in[12];

    int S = in_sizes[0];                 // encoder sequence length (2048)
    int V = in_sizes[12];                // vocab out (50257)
    int D = out_size / V;                // decoder steps (512)
    int TS = S + D;
    float* out = (float*)d_out;

    size_t initElems = (size_t)(TS + 1) * Hdim;
    init_kernel<<<(int)((initElems + 255) / 256), 256>>>(TS);

    xp_gemm_tc<<<dim3((S + 127) / 128, GATES / 128), 256>>>(state, enc_Wih, emb,
                                                            enc_bih, enc_bhh, S);

    recur<<<G_CTAS, 256>>>(enc_Whh, dec_Whh, dec_bih, dec_bhh, S, D);

    out_gemm_tc<<<dim3((V + 127) / 128, (D + 127) / 128), 256>>>(Wout, bout, out,
                                                                 S + 1, D, V);

    softmax_rows<<<D, 256>>>(out, V);
}

// round 12
// speedup vs baseline: 1.0143x; 1.0143x over previous
#include <cuda_runtime.h>
#include <math.h>
#include <stdint.h>

#define Hdim   1024
#define Edim   512
#define GATES  4096          // 4*Hdim
#define MAXS   2048
#define MAXD   512
#define G_CTAS 128           // Hdim/8 CTAs, all resident (<=148 SMs)
#define POISON 0x7FBFFFFFu   // NaN bit pattern; h=o*tanh(c) can never be NaN

// ---------------- persistent device state ----------------
__device__ __align__(16) float d_Xp[(size_t)MAXS * GATES];               // encoder input projections (+bias)
__device__ __align__(16) float d_Hbuf[(size_t)(MAXS + MAXD + 1) * Hdim]; // h_t for every step (step-indexed)

// ---------------- init: zero h0, poison h1..hTS (data-is-the-flag sync) ----------------
__global__ void init_kernel(int total_steps) {
    size_t i = (size_t)blockIdx.x * blockDim.x + threadIdx.x;
    size_t tot = (size_t)(total_steps + 1) * Hdim;
    if (i < Hdim) d_Hbuf[i] = 0.0f;
    else if (i < tot) ((uint32_t*)d_Hbuf)[i] = POISON;
}

// ---------------- tf32 helpers ----------------
__device__ __forceinline__ uint32_t f2tf32(float x) {
    uint32_t u;
    asm("cvt.rna.tf32.f32 %0, %1;" : "=r"(u) : "f"(x));
    return u;
}

__device__ __forceinline__ void mma_tf32(float d[4], const uint32_t a[4],
                                         const uint32_t b[2]) {
    asm volatile("mma.sync.aligned.m16n8k8.row.col.f32.tf32.tf32.f32 "
                 "{%0,%1,%2,%3}, {%4,%5,%6,%7}, {%8,%9}, {%0,%1,%2,%3};"
                 : "+f"(d[0]), "+f"(d[1]), "+f"(d[2]), "+f"(d[3])
                 : "r"(a[0]), "r"(a[1]), "r"(a[2]), "r"(a[3]),
                   "r"(b[0]), "r"(b[1]));
}

#define OG_STR 36
#define STAGE_WORDS (128 * OG_STR)

// ---------------- Xp GEMM (tf32): Xp[t][r] = Wih[r,:].emb[state[t],:] + b[r] ----------------
__global__ __launch_bounds__(256, 2) void xp_gemm_tc(const int* __restrict__ state,
                                                     const float* __restrict__ Wih,
                                                     const float* __restrict__ emb,
                                                     const float* __restrict__ bih,
                                                     const float* __restrict__ bhh,
                                                     int S) {
    __shared__ uint32_t As[STAGE_WORDS];
    __shared__ uint32_t Bs[STAGE_WORDS];

    int bn = blockIdx.x, bm = blockIdx.y;
    int tid = threadIdx.x;
    int warp = tid >> 5;
    int lane = tid & 31;
    int grp = lane >> 2;
    int tg  = lane & 3;
    int wm = (warp & 1) * 64;
    int wn = (warp >> 1) * 32;

    int lr = tid >> 1;
    int part = (tid & 1) * 16;

    const float* Aptr = Wih + (size_t)(bm * 128 + lr) * Edim + part;
    int nrow = bn * 128 + lr; if (nrow >= S) nrow = S - 1;
    const float* Bptr = emb + (size_t)state[nrow] * Edim + part;

    float d[4][4][4];
#pragma unroll
    for (int i = 0; i < 4; i++)
#pragma unroll
        for (int j = 0; j < 4; j++)
#pragma unroll
            for (int k = 0; k < 4; k++) d[i][j][k] = 0.0f;

    for (int k0 = 0; k0 < Edim; k0 += 32) {
#pragma unroll
        for (int i = 0; i < 4; i++) {
            float4 av = *(const float4*)(Aptr + k0 + i * 4);
            float4 bv = *(const float4*)(Bptr + k0 + i * 4);
            uint32_t* ad = &As[lr * OG_STR + part + i * 4];
            uint32_t* bd = &Bs[lr * OG_STR + part + i * 4];
            ad[0] = f2tf32(av.x); ad[1] = f2tf32(av.y);
            ad[2] = f2tf32(av.z); ad[3] = f2tf32(av.w);
            bd[0] = f2tf32(bv.x); bd[1] = f2tf32(bv.y);
            bd[2] = f2tf32(bv.z); bd[3] = f2tf32(bv.w);
        }
        __syncthreads();

#pragma unroll
        for (int kk = 0; kk < 32; kk += 8) {
            uint32_t fb[4][2];
#pragma unroll
            for (int na = 0; na < 4; na++) {
                int n = wn + na * 8 + grp;
                fb[na][0] = Bs[n * OG_STR + kk + tg];
                fb[na][1] = Bs[n * OG_STR + kk + tg + 4];
            }
            uint32_t fa[4][4];
#pragma unroll
            for (int ma = 0; ma < 4; ma++) {
                int m = wm + ma * 16;
                fa[ma][0] = As[(m + grp) * OG_STR + kk + tg];
                fa[ma][1] = As[(m + 8 + grp) * OG_STR + kk + tg];
                fa[ma][2] = As[(m + grp) * OG_STR + kk + tg + 4];
                fa[ma][3] = As[(m + 8 + grp) * OG_STR + kk + tg + 4];
            }
#pragma unroll
            for (int ma = 0; ma < 4; ma++)
#pragma unroll
                for (int na = 0; na < 4; na++)
                    mma_tf32(d[ma][na], fa[ma], fb[na]);
        }
        __syncthreads();
    }

    // transposed epilogue: Xp[t][r] = d + bias[r]
#pragma unroll
    for (int ma = 0; ma < 4; ma++) {
        int m0 = bm * 128 + wm + ma * 16 + grp;
        float b0 = bih[m0] + bhh[m0];
        float b1 = bih[m0 + 8] + bhh[m0 + 8];
#pragma unroll
        for (int na = 0; na < 4; na++) {
            int n0 = bn * 128 + wn + na * 8 + tg * 2;
            if (n0 < S) {
                float* xr = d_Xp + (size_t)n0 * GATES;
                xr[m0]     = d[ma][na][0] + b0;
                xr[m0 + 8] = d[ma][na][2] + b1;
            }
            if (n0 + 1 < S) {
                float* xr = d_Xp + (size_t)(n0 + 1) * GATES;
                xr[m0]     = d[ma][na][1] + b0;
                xr[m0 + 8] = d[ma][na][3] + b1;
            }
        }
    }
}

// ---------------- persistent recurrence kernel (R10-exact — known good) ----------------
__device__ __forceinline__ float sigmoid_f(float x) { return 1.0f / (1.0f + __expf(-x)); }
__device__ __forceinline__ float tanh_f(float x) { return 1.0f - 2.0f / (__expf(2.0f * x) + 1.0f); }

__global__ __launch_bounds__(256, 1) void recur(const float* __restrict__ encWhh,
                                                const float* __restrict__ decWhh,
                                                const float* __restrict__ dbih,
                                                const float* __restrict__ dbhh,
                                                int S, int D) {
    __shared__ float4 hs4[8 * 33];   // padded h (33 float4 per 32-float4 segment)
    __shared__ float  g_s[32];
    __shared__ float  c_s[8];

    int tid = threadIdx.x;
    int b = blockIdx.x;
    int seg = tid & 7;
    int rl = tid >> 3;               // 0..31
    int gate = rl >> 3, q = rl & 7;
    int R = gate * 1024 + b * 8 + q;

    if (tid < 8) c_s[tid] = 0.0f;

    float4 w[32];
    {
        const float4* src = (const float4*)(encWhh + (size_t)R * Hdim + seg * 128);
#pragma unroll
        for (int k = 0; k < 32; k++) w[k] = src[k];
    }
    float decB = 0.0f;
    if (seg == 0) decB = dbih[R] + dbhh[R];

    int TS = S + D;
    for (int t = 0; t < TS; t++) {
        if (t == S) {  // switch to decoder weights
            const float4* src = (const float4*)(decWhh + (size_t)R * Hdim + seg * 128);
#pragma unroll
            for (int k = 0; k < 32; k++) w[k] = src[k];
        }

        // issue per-row additive term load EARLY (DRAM latency overlaps the poll)
        float extra = 0.0f;
        if (seg == 0) extra = (t < S) ? d_Xp[(size_t)t * GATES + R] : decB;

        // data-is-the-flag: spin on OUR 16B of h_t until all 4 lanes non-poison.
        uint32_t x0, x1, x2, x3;
        {
            const uint32_t* hp = (const uint32_t*)(d_Hbuf + (size_t)t * Hdim) + tid * 4;
            do {
                asm volatile("ld.relaxed.gpu.global.v4.u32 {%0,%1,%2,%3}, [%4];"
                             : "=r"(x0), "=r"(x1), "=r"(x2), "=r"(x3) : "l"(hp));
            } while (x0 == POISON || x1 == POISON || x2 == POISON || x3 == POISON);
        }
        {
            float4 hv;
            hv.x = __uint_as_float(x0); hv.y = __uint_as_float(x1);
            hv.z = __uint_as_float(x2); hv.w = __uint_as_float(x3);
            hs4[tid + (tid >> 5)] = hv;
        }
        __syncthreads();

        // 128-wide partial dot from register weights (4 independent chains)
        float a0 = 0, a1 = 0, a2 = 0, a3 = 0;
#pragma unroll
        for (int k = 0; k < 32; k += 2) {
            float4 h0 = hs4[seg * 33 + k];
            float4 h1 = hs4[seg * 33 + k + 1];
            a0 += w[k].x * h0.x;  a1 += w[k].y * h0.y;
            a2 += w[k].z * h0.z;  a3 += w[k].w * h0.w;
            a0 += w[k + 1].x * h1.x;  a1 += w[k + 1].y * h1.y;
            a2 += w[k + 1].z * h1.z;  a3 += w[k + 1].w * h1.w;
        }
        float acc = (a0 + a1) + (a2 + a3);
        acc += __shfl_xor_sync(0xffffffffu, acc, 1);
        acc += __shfl_xor_sync(0xffffffffu, acc, 2);
        acc += __shfl_xor_sync(0xffffffffu, acc, 4);
        if (seg == 0) g_s[rl] = acc + extra;
        __syncthreads();

        // LSTM cell: 32 lanes compute 4 gate activations in parallel, 8 finish
        if (tid < 32) {
            float gv = g_s[tid];
            float act = ((tid >> 3) == 2) ? tanh_f(gv) : sigmoid_f(gv);
            int qq = tid & 7;
            float a_i = __shfl_sync(0xffffffffu, act, qq);
            float a_f = __shfl_sync(0xffffffffu, act, 8 + qq);
            float a_g = __shfl_sync(0xffffffffu, act, 16 + qq);
            float a_o = __shfl_sync(0xffffffffu, act, 24 + qq);
            if (tid < 8) {
                float c = a_f * c_s[tid] + a_i * a_g;
                c_s[tid] = c;
                float h = a_o * tanh_f(c);
                float* hw = d_Hbuf + (size_t)(t + 1) * Hdim + b * 8 + tid;
                asm volatile("st.relaxed.gpu.global.f32 [%0], %1;"
                             :: "l"(hw), "f"(h) : "memory");
            }
        }
        // no global counter, no fence: next iteration's poll is the sync
    }
}

// ---------------- output GEMM (tf32 tensor cores, 2-stage cp.async pipeline) ----------------
// dynamic smem: [2][As STAGE_WORDS][Bs STAGE_WORDS] raw f32; tf32 cvt at fragment load.
__global__ __launch_bounds__(256, 2) void out_gemm_tc(const float* __restrict__ Wout,
                                                      const float* __restrict__ bout,
                                                      float* __restrict__ out,
                                                      int hoff, int M, int N) {
    extern __shared__ float smem_f[];
    float* AsBase = smem_f;                       // 2 stages
    float* BsBase = smem_f + 2 * STAGE_WORDS;     // 2 stages

    int bn = blockIdx.x, bm = blockIdx.y;
    int tid = threadIdx.x;
    int warp = tid >> 5;
    int lane = tid & 31;
    int grp = lane >> 2;
    int tg  = lane & 3;
    int wm = (warp & 1) * 64;
    int wn = (warp >> 1) * 32;

    int lr = tid >> 1;
    int part = (tid & 1) * 16;

    const float* Aptr = d_Hbuf + (size_t)(hoff + bm * 128 + lr) * Hdim + part;
    int nrow = bn * 128 + lr; if (nrow >= N) nrow = N - 1;
    const float* Bptr = Wout + (size_t)nrow * Hdim + part;

    uint32_t a_dst0 = (uint32_t)__cvta_generic_to_shared(AsBase + lr * OG_STR + part);
    uint32_t b_dst0 = (uint32_t)__cvta_generic_to_shared(BsBase + lr * OG_STR + part);

    float d[4][4][4];
#pragma unroll
    for (int i = 0; i < 4; i++)
#pragma unroll
        for (int j = 0; j < 4; j++)
#pragma unroll
            for (int k = 0; k < 4; k++) d[i][j][k] = 0.0f;

    const int NK = Hdim / 32;   // 32 k-chunks

    // prologue: stage 0
    {
#pragma unroll
        for (int i = 0; i < 4; i++) {
            asm volatile("cp.async.ca.shared.global [%0], [%1], 16;"
                         :: "r"(a_dst0 + i * 16), "l"(Aptr + i * 4));
            asm volatile("cp.async.ca.shared.global [%0], [%1], 16;"
                         :: "r"(b_dst0 + i * 16), "l"(Bptr + i * 4));
        }
        asm volatile("cp.async.commit_group;");
    }

    for (int it = 0; it < NK; it++) {
        if (it + 1 < NK) {
            int s = (it + 1) & 1;
            uint32_t ad = a_dst0 + s * (STAGE_WORDS * 4);
            uint32_t bd = b_dst0 + s * (STAGE_WORDS * 4);
            const float* Ap = Aptr + (it + 1) * 32;
            const float* Bp = Bptr + (it + 1) * 32;
#pragma unroll
            for (int i = 0; i < 4; i++) {
                asm volatile("cp.async.ca.shared.global [%0], [%1], 16;"
                             :: "r"(ad + i * 16), "l"(Ap + i * 4));
                asm volatile("cp.async.ca.shared.global [%0], [%1], 16;"
                             :: "r"(bd + i * 16), "l"(Bp + i * 4));
            }
            asm volatile("cp.async.commit_group;");
            asm volatile("cp.async.wait_group 1;");
        } else {
            asm volatile("cp.async.wait_group 0;");
        }
        __syncthreads();

        const float* Asf = AsBase + (it & 1) * STAGE_WORDS;
        const float* Bsf = BsBase + (it & 1) * STAGE_WORDS;

#pragma unroll
        for (int kk = 0; kk < 32; kk += 8) {
            uint32_t fb[4][2];
#pragma unroll
            for (int na = 0; na < 4; na++) {
                int n = wn + na * 8 + grp;
                fb[na][0] = f2tf32(Bsf[n * OG_STR + kk + tg]);
                fb[na][1] = f2tf32(Bsf[n * OG_STR + kk + tg + 4]);
            }
            uint32_t fa[4][4];
#pragma unroll
            for (int ma = 0; ma < 4; ma++) {
                int m = wm + ma * 16;
                fa[ma][0] = f2tf32(Asf[(m + grp) * OG_STR + kk + tg]);
                fa[ma][1] = f2tf32(Asf[(m + 8 + grp) * OG_STR + kk + tg]);
                fa[ma][2] = f2tf32(Asf[(m + grp) * OG_STR + kk + tg + 4]);
                fa[ma][3] = f2tf32(Asf[(m + 8 + grp) * OG_STR + kk + tg + 4]);
            }
#pragma unroll
            for (int ma = 0; ma < 4; ma++)
#pragma unroll
                for (int na = 0; na < 4; na++)
                    mma_tf32(d[ma][na], fa[ma], fb[na]);
        }
        __syncthreads();
    }

    // epilogue: scalar stores (N odd -> rows only 4B aligned)
#pragma unroll
    for (int ma = 0; ma < 4; ma++) {
        int m0 = bm * 128 + wm + ma * 16 + grp;
        float* r0 = out + (size_t)m0 * N;
        float* r1 = out + (size_t)(m0 + 8) * N;
#pragma unroll
        for (int na = 0; na < 4; na++) {
            int n0 = bn * 128 + wn + na * 8 + tg * 2;
            if (n0 < N) {
                float bb = bout[n0];
                r0[n0] = d[ma][na][0] + bb;
                r1[n0] = d[ma][na][2] + bb;
            }
            if (n0 + 1 < N) {
                float bb = bout[n0 + 1];
                r0[n0 + 1] = d[ma][na][1] + bb;
                r1[n0 + 1] = d[ma][na][3] + bb;
            }
        }
    }
}

// ---------------- row softmax (in place) ----------------
__global__ void softmax_rows(float* __restrict__ out, int N) {
    int row = blockIdx.x;
    float* p = out + (size_t)row * N;
    int tid = threadIdx.x;
    __shared__ float red[256];

    float mx = -1e30f;
    for (int i = tid; i < N; i += 256) mx = fmaxf(mx, p[i]);
    red[tid] = mx; __syncthreads();
    for (int s = 128; s > 0; s >>= 1) {
        if (tid < s) red[tid] = fmaxf(red[tid], red[tid + s]);
        __syncthreads();
    }
    mx = red[0]; __syncthreads();

    float sum = 0.0f;
    for (int i = tid; i < N; i += 256) sum += __expf(p[i] - mx);
    red[tid] = sum; __syncthreads();
    for (int s = 128; s > 0; s >>= 1) {
        if (tid < s) red[tid] += red[tid + s];
        __syncthreads();
    }
    float inv = 1.0f / red[0];

    for (int i = tid; i < N; i += 256) p[i] = __expf(p[i] - mx) * inv;
}

// ---------------- launch ----------------
extern "C" void kernel_launch(void* const* d_in, const int* in_sizes, int n_in,
                              void* d_out, int out_size) {
    const int*   state   = (const int*)d_in[0];
    const float* emb     = (const float*)d_in[2];
    const float* enc_Wih = (const float*)d_in[3];
    const float* enc_Whh = (const float*)d_in[4];
    const float* enc_bih = (const float*)d_in[5];
    const float* enc_bhh = (const float*)d_in[6];
    const float* dec_Whh = (const float*)d_in[8];
    const float* dec_bih = (const float*)d_in[9];
    const float* dec_bhh = (const float*)d_in[10];
    const float* Wout    = (const float*)d_in[11];
    const float* bout    = (const float*)d_in[12];

    int S = in_sizes[0];                 // encoder sequence length (2048)
    int V = in_sizes[12];                // vocab out (50257)
    int D = out_size / V;                // decoder steps (512)
    int TS = S + D;
    float* out = (float*)d_out;

    size_t initElems = (size_t)(TS + 1) * Hdim;
    init_kernel<<<(int)((initElems + 255) / 256), 256>>>(TS);

    xp_gemm_tc<<<dim3((S + 127) / 128, GATES / 128), 256>>>(state, enc_Wih, emb,
                                                            enc_bih, enc_bhh, S);

    recur<<<G_CTAS, 256>>>(enc_Whh, dec_Whh, dec_bih, dec_bhh, S, D);

    const int OG_SMEM = 4 * STAGE_WORDS * (int)sizeof(float);   // 73728 B
    static int smem_set = 0;
    if (!smem_set) {
        cudaFuncSetAttribute(out_gemm_tc,
                             cudaFuncAttributeMaxDynamicSharedMemorySize, OG_SMEM);
        smem_set = 1;
    }
    out_gemm_tc<<<dim3((V + 127) / 128, (D + 127) / 128), 256, OG_SMEM>>>(
        Wout, bout, out, S + 1, D, V);

    softmax_rows<<<D, 256>>>(out, V);
}

// round 14
// speedup vs baseline: 1.4510x; 1.4306x over previous
#include <cuda_runtime.h>
#include <math.h>
#include <stdint.h>

#define Hdim   1024
#define Edim   512
#define GATES  4096          // 4*Hdim
#define MAXS   2048
#define MAXD   512
#define G_CTAS 128           // Hdim/8 CTAs, all resident (<=148 SMs)
#define POISON 0x7FBFFFFFu   // NaN bit pattern; h=o*tanh(c) can never be NaN

// ---------------- persistent device state ----------------
__device__ __align__(16) float d_Xp[(size_t)MAXS * GATES];               // encoder input projections (+bias)
__device__ __align__(16) float d_Hbuf[(size_t)(MAXS + MAXD + 1) * Hdim]; // h_t for every step (step-indexed)

// ---------------- init: zero h0, poison h1..hTS (data-is-the-flag sync) ----------------
__global__ void init_kernel(int total_steps) {
    size_t i = (size_t)blockIdx.x * blockDim.x + threadIdx.x;
    size_t tot = (size_t)(total_steps + 1) * Hdim;
    if (i < Hdim) d_Hbuf[i] = 0.0f;
    else if (i < tot) ((uint32_t*)d_Hbuf)[i] = POISON;
}

// ---------------- tf32 helpers ----------------
__device__ __forceinline__ uint32_t f2tf32(float x) {
    uint32_t u;
    asm("cvt.rna.tf32.f32 %0, %1;" : "=r"(u) : "f"(x));
    return u;
}

__device__ __forceinline__ void mma_tf32(float d[4], const uint32_t a[4],
                                         const uint32_t b[2]) {
    asm volatile("mma.sync.aligned.m16n8k8.row.col.f32.tf32.tf32.f32 "
                 "{%0,%1,%2,%3}, {%4,%5,%6,%7}, {%8,%9}, {%0,%1,%2,%3};"
                 : "+f"(d[0]), "+f"(d[1]), "+f"(d[2]), "+f"(d[3])
                 : "r"(a[0]), "r"(a[1]), "r"(a[2]), "r"(a[3]),
                   "r"(b[0]), "r"(b[1]));
}

#define OG_STR 36

// ---------------- Xp GEMM (tf32): Xp[t][r] = Wih[r,:].emb[state[t],:] + b[r] ----------------
__global__ __launch_bounds__(256, 2) void xp_gemm_tc(const int* __restrict__ state,
                                                     const float* __restrict__ Wih,
                                                     const float* __restrict__ emb,
                                                     const float* __restrict__ bih,
                                                     const float* __restrict__ bhh,
                                                     int S) {
    __shared__ uint32_t As[128 * OG_STR];
    __shared__ uint32_t Bs[128 * OG_STR];

    int bn = blockIdx.x, bm = blockIdx.y;
    int tid = threadIdx.x;
    int warp = tid >> 5;
    int lane = tid & 31;
    int grp = lane >> 2;
    int tg  = lane & 3;
    int wm = (warp & 1) * 64;
    int wn = (warp >> 1) * 32;

    int lr = tid >> 1;
    int part = (tid & 1) * 16;

    const float* Aptr = Wih + (size_t)(bm * 128 + lr) * Edim + part;
    int nrow = bn * 128 + lr; if (nrow >= S) nrow = S - 1;
    const float* Bptr = emb + (size_t)state[nrow] * Edim + part;

    float d[4][4][4];
#pragma unroll
    for (int i = 0; i < 4; i++)
#pragma unroll
        for (int j = 0; j < 4; j++)
#pragma unroll
            for (int k = 0; k < 4; k++) d[i][j][k] = 0.0f;

    for (int k0 = 0; k0 < Edim; k0 += 32) {
#pragma unroll
        for (int i = 0; i < 4; i++) {
            float4 av = *(const float4*)(Aptr + k0 + i * 4);
            float4 bv = *(const float4*)(Bptr + k0 + i * 4);
            uint32_t* ad = &As[lr * OG_STR + part + i * 4];
            uint32_t* bd = &Bs[lr * OG_STR + part + i * 4];
            ad[0] = f2tf32(av.x); ad[1] = f2tf32(av.y);
            ad[2] = f2tf32(av.z); ad[3] = f2tf32(av.w);
            bd[0] = f2tf32(bv.x); bd[1] = f2tf32(bv.y);
            bd[2] = f2tf32(bv.z); bd[3] = f2tf32(bv.w);
        }
        __syncthreads();

#pragma unroll
        for (int kk = 0; kk < 32; kk += 8) {
            uint32_t fb[4][2];
#pragma unroll
            for (int na = 0; na < 4; na++) {
                int n = wn + na * 8 + grp;
                fb[na][0] = Bs[n * OG_STR + kk + tg];
                fb[na][1] = Bs[n * OG_STR + kk + tg + 4];
            }
            uint32_t fa[4][4];
#pragma unroll
            for (int ma = 0; ma < 4; ma++) {
                int m = wm + ma * 16;
                fa[ma][0] = As[(m + grp) * OG_STR + kk + tg];
                fa[ma][1] = As[(m + 8 + grp) * OG_STR + kk + tg];
                fa[ma][2] = As[(m + grp) * OG_STR + kk + tg + 4];
                fa[ma][3] = As[(m + 8 + grp) * OG_STR + kk + tg + 4];
            }
#pragma unroll
            for (int ma = 0; ma < 4; ma++)
#pragma unroll
                for (int na = 0; na < 4; na++)
                    mma_tf32(d[ma][na], fa[ma], fb[na]);
        }
        __syncthreads();
    }

    // transposed epilogue: Xp[t][r] = d + bias[r]
#pragma unroll
    for (int ma = 0; ma < 4; ma++) {
        int m0 = bm * 128 + wm + ma * 16 + grp;
        float b0 = bih[m0] + bhh[m0];
        float b1 = bih[m0 + 8] + bhh[m0 + 8];
#pragma unroll
        for (int na = 0; na < 4; na++) {
            int n0 = bn * 128 + wn + na * 8 + tg * 2;
            if (n0 < S) {
                float* xr = d_Xp + (size_t)n0 * GATES;
                xr[m0]     = d[ma][na][0] + b0;
                xr[m0 + 8] = d[ma][na][2] + b1;
            }
            if (n0 + 1 < S) {
                float* xr = d_Xp + (size_t)(n0 + 1) * GATES;
                xr[m0]     = d[ma][na][1] + b0;
                xr[m0 + 8] = d[ma][na][3] + b1;
            }
        }
    }
}

// ---------------- persistent recurrence kernel (R10-exact — known good) ----------------
__device__ __forceinline__ float sigmoid_f(float x) { return 1.0f / (1.0f + __expf(-x)); }
__device__ __forceinline__ float tanh_f(float x) { return 1.0f - 2.0f / (__expf(2.0f * x) + 1.0f); }

__global__ __launch_bounds__(256, 1) void recur(const float* __restrict__ encWhh,
                                                const float* __restrict__ decWhh,
                                                const float* __restrict__ dbih,
                                                const float* __restrict__ dbhh,
                                                int S, int D) {
    __shared__ float4 hs4[8 * 33];   // padded h (33 float4 per 32-float4 segment)
    __shared__ float  g_s[32];
    __shared__ float  c_s[8];

    int tid = threadIdx.x;
    int b = blockIdx.x;
    int seg = tid & 7;
    int rl = tid >> 3;               // 0..31
    int gate = rl >> 3, q = rl & 7;
    int R = gate * 1024 + b * 8 + q;

    if (tid < 8) c_s[tid] = 0.0f;

    float4 w[32];
    {
        const float4* src = (const float4*)(encWhh + (size_t)R * Hdim + seg * 128);
#pragma unroll
        for (int k = 0; k < 32; k++) w[k] = src[k];
    }
    float decB = 0.0f;
    if (seg == 0) decB = dbih[R] + dbhh[R];

    int TS = S + D;
    for (int t = 0; t < TS; t++) {
        if (t == S) {  // switch to decoder weights
            const float4* src = (const float4*)(decWhh + (size_t)R * Hdim + seg * 128);
#pragma unroll
            for (int k = 0; k < 32; k++) w[k] = src[k];
        }

        // issue per-row additive term load EARLY (DRAM latency overlaps the poll)
        float extra = 0.0f;
        if (seg == 0) extra = (t < S) ? d_Xp[(size_t)t * GATES + R] : decB;

        // data-is-the-flag: spin on OUR 16B of h_t until all 4 lanes non-poison.
        uint32_t x0, x1, x2, x3;
        {
            const uint32_t* hp = (const uint32_t*)(d_Hbuf + (size_t)t * Hdim) + tid * 4;
            do {
                asm volatile("ld.relaxed.gpu.global.v4.u32 {%0,%1,%2,%3}, [%4];"
                             : "=r"(x0), "=r"(x1), "=r"(x2), "=r"(x3) : "l"(hp));
            } while (x0 == POISON || x1 == POISON || x2 == POISON || x3 == POISON);
        }
        {
            float4 hv;
            hv.x = __uint_as_float(x0); hv.y = __uint_as_float(x1);
            hv.z = __uint_as_float(x2); hv.w = __uint_as_float(x3);
            hs4[tid + (tid >> 5)] = hv;
        }
        __syncthreads();

        // 128-wide partial dot from register weights (4 independent chains)
        float a0 = 0, a1 = 0, a2 = 0, a3 = 0;
#pragma unroll
        for (int k = 0; k < 32; k += 2) {
            float4 h0 = hs4[seg * 33 + k];
            float4 h1 = hs4[seg * 33 + k + 1];
            a0 += w[k].x * h0.x;  a1 += w[k].y * h0.y;
            a2 += w[k].z * h0.z;  a3 += w[k].w * h0.w;
            a0 += w[k + 1].x * h1.x;  a1 += w[k + 1].y * h1.y;
            a2 += w[k + 1].z * h1.z;  a3 += w[k + 1].w * h1.w;
        }
        float acc = (a0 + a1) + (a2 + a3);
        acc += __shfl_xor_sync(0xffffffffu, acc, 1);
        acc += __shfl_xor_sync(0xffffffffu, acc, 2);
        acc += __shfl_xor_sync(0xffffffffu, acc, 4);
        if (seg == 0) g_s[rl] = acc + extra;
        __syncthreads();

        // LSTM cell: 32 lanes compute 4 gate activations in parallel, 8 finish
        if (tid < 32) {
            float gv = g_s[tid];
            float act = ((tid >> 3) == 2) ? tanh_f(gv) : sigmoid_f(gv);
            int qq = tid & 7;
            float a_i = __shfl_sync(0xffffffffu, act, qq);
            float a_f = __shfl_sync(0xffffffffu, act, 8 + qq);
            float a_g = __shfl_sync(0xffffffffu, act, 16 + qq);
            float a_o = __shfl_sync(0xffffffffu, act, 24 + qq);
            if (tid < 8) {
                float c = a_f * c_s[tid] + a_i * a_g;
                c_s[tid] = c;
                float h = a_o * tanh_f(c);
                float* hw = d_Hbuf + (size_t)(t + 1) * Hdim + b * 8 + tid;
                asm volatile("st.relaxed.gpu.global.f32 [%0], %1;"
                             :: "l"(hw), "f"(h) : "memory");
            }
        }
        // no global counter, no fence: next iteration's poll is the sync
    }
}

// ---------------- output GEMM (tf32 tensor cores, R10-exact) ----------------
__global__ __launch_bounds__(256, 2) void out_gemm_tc(const float* __restrict__ Wout,
                                                      const float* __restrict__ bout,
                                                      float* __restrict__ out,
                                                      int hoff, int M, int N) {
    __shared__ uint32_t As[128 * OG_STR];
    __shared__ uint32_t Bs[128 * OG_STR];

    int bn = blockIdx.x, bm = blockIdx.y;
    int tid = threadIdx.x;
    int warp = tid >> 5;
    int lane = tid & 31;
    int grp = lane >> 2;
    int tg  = lane & 3;
    int wm = (warp & 1) * 64;
    int wn = (warp >> 1) * 32;

    int lr = tid >> 1;
    int part = (tid & 1) * 16;

    const float* Aptr = d_Hbuf + (size_t)(hoff + bm * 128 + lr) * Hdim + part;
    int nrow = bn * 128 + lr; if (nrow >= N) nrow = N - 1;
    const float* Bptr = Wout + (size_t)nrow * Hdim + part;

    float d[4][4][4];
#pragma unroll
    for (int i = 0; i < 4; i++)
#pragma unroll
        for (int j = 0; j < 4; j++)
#pragma unroll
            for (int k = 0; k < 4; k++) d[i][j][k] = 0.0f;

    for (int k0 = 0; k0 < Hdim; k0 += 32) {
#pragma unroll
        for (int i = 0; i < 4; i++) {
            float4 av = *(const float4*)(Aptr + k0 + i * 4);
            float4 bv = *(const float4*)(Bptr + k0 + i * 4);
            uint32_t* ad = &As[lr * OG_STR + part + i * 4];
            uint32_t* bd = &Bs[lr * OG_STR + part + i * 4];
            ad[0] = f2tf32(av.x); ad[1] = f2tf32(av.y);
            ad[2] = f2tf32(av.z); ad[3] = f2tf32(av.w);
            bd[0] = f2tf32(bv.x); bd[1] = f2tf32(bv.y);
            bd[2] = f2tf32(bv.z); bd[3] = f2tf32(bv.w);
        }
        __syncthreads();

#pragma unroll
        for (int kk = 0; kk < 32; kk += 8) {
            uint32_t fb[4][2];
#pragma unroll
            for (int na = 0; na < 4; na++) {
                int n = wn + na * 8 + grp;
                fb[na][0] = Bs[n * OG_STR + kk + tg];
                fb[na][1] = Bs[n * OG_STR + kk + tg + 4];
            }
            uint32_t fa[4][4];
#pragma unroll
            for (int ma = 0; ma < 4; ma++) {
                int m = wm + ma * 16;
                fa[ma][0] = As[(m + grp) * OG_STR + kk + tg];
                fa[ma][1] = As[(m + 8 + grp) * OG_STR + kk + tg];
                fa[ma][2] = As[(m + grp) * OG_STR + kk + tg + 4];
                fa[ma][3] = As[(m + 8 + grp) * OG_STR + kk + tg + 4];
            }
#pragma unroll
            for (int ma = 0; ma < 4; ma++)
#pragma unroll
                for (int na = 0; na < 4; na++)
                    mma_tf32(d[ma][na], fa[ma], fb[na]);
        }
        __syncthreads();
    }

    // epilogue: scalar stores (N odd -> rows only 4B aligned)
#pragma unroll
    for (int ma = 0; ma < 4; ma++) {
        int m0 = bm * 128 + wm + ma * 16 + grp;
        float* r0 = out + (size_t)m0 * N;
        float* r1 = out + (size_t)(m0 + 8) * N;
#pragma unroll
        for (int na = 0; na < 4; na++) {
            int n0 = bn * 128 + wn + na * 8 + tg * 2;
            if (n0 < N) {
                float bb = bout[n0];
                r0[n0] = d[ma][na][0] + bb;
                r1[n0] = d[ma][na][2] + bb;
            }
            if (n0 + 1 < N) {
                float bb = bout[n0 + 1];
                r0[n0 + 1] = d[ma][na][1] + bb;
                r1[n0 + 1] = d[ma][na][3] + bb;
            }
        }
    }
}

// ---------------- row softmax (in place, single-exp: store e in pass 2) ----------------
__global__ void softmax_rows(float* __restrict__ out, int N) {
    int row = blockIdx.x;
    float* p = out + (size_t)row * N;
    int tid = threadIdx.x;
    __shared__ float red[256];

    float mx = -1e30f;
    for (int i = tid; i < N; i += 256) mx = fmaxf(mx, p[i]);
    red[tid] = mx; __syncthreads();
    for (int s = 128; s > 0; s >>= 1) {
        if (tid < s) red[tid] = fmaxf(red[tid], red[tid + s]);
        __syncthreads();
    }
    mx = red[0]; __syncthreads();

    // pass 2: compute e once, store it, accumulate sum (halves MUFU work)
    float sum = 0.0f;
    for (int i = tid; i < N; i += 256) {
        float e = __expf(p[i] - mx);
        p[i] = e;
        sum += e;
    }
    red[tid] = sum; __syncthreads();
    for (int s = 128; s > 0; s >>= 1) {
        if (tid < s) red[tid] += red[tid + s];
        __syncthreads();
    }
    float inv = 1.0f / red[0];

    // pass 3: pure scale (no exp)
    for (int i = tid; i < N; i += 256) p[i] *= inv;
}

// ---------------- launch ----------------
extern "C" void kernel_launch(void* const* d_in, const int* in_sizes, int n_in,
                              void* d_out, int out_size) {
    const int*   state   = (const int*)d_in[0];
    const float* emb     = (const float*)d_in[2];
    const float* enc_Wih = (const float*)d_in[3];
    const float* enc_Whh = (const float*)d_in[4];
    const float* enc_bih = (const float*)d_in[5];
    const float* enc_bhh = (const float*)d_in[6];
    const float* dec_Whh = (const float*)d_in[8];
    const float* dec_bih = (const float*)d_in[9];
    const float* dec_bhh = (const float*)d_in[10];
    const float* Wout    = (const float*)d_in[11];
    const float* bout    = (const float*)d_in[12];

    int S = in_sizes[0];                 // encoder sequence length (2048)
    int V = in_sizes[12];                // vocab out (50257)
    int D = out_size / V;                // decoder steps (512)
    int TS = S + D;
    float* out = (float*)d_out;

    size_t initElems = (size_t)(TS + 1) * Hdim;
    init_kernel<<<(int)((initElems + 255) / 256), 256>>>(TS);

    xp_gemm_tc<<<dim3((S + 127) / 128, GATES / 128), 256>>>(state, enc_Wih, emb,
                                                            enc_bih, enc_bhh, S);

    recur<<<G_CTAS, 256>>>(enc_Whh, dec_Whh, dec_bih, dec_bhh, S, D);

    out_gemm_tc<<<dim3((V + 127) / 128, (D + 127) / 128), 256>>>(Wout, bout, out,
                                                                 S + 1, D, V);

    softmax_rows<<<D, 256>>>(out, V);
}

// round 15
// speedup vs baseline: 1.4993x; 1.0333x over previous
#include <cuda_runtime.h>
#include <math.h>
#include <stdint.h>

#define Hdim   1024
#define Edim   512
#define GATES  4096          // 4*Hdim
#define MAXS   2048
#define MAXD   512
#define G_CTAS 128           // Hdim/8 CTAs, all resident (<=148 SMs)
#define POISON 0x7FBFFFFFu   // NaN bit pattern; h=o*tanh(c) can never be NaN

// ---------------- persistent device state ----------------
__device__ __align__(16) float d_Xp[(size_t)MAXS * GATES];               // encoder input projections (+bias)
__device__ __align__(16) float d_Hbuf[(size_t)(MAXS + MAXD + 1) * Hdim]; // h_t for every step (step-indexed)

// ---------------- init: zero h0, poison h1..hTS (data-is-the-flag sync) ----------------
__global__ void init_kernel(int total_steps) {
    size_t i = (size_t)blockIdx.x * blockDim.x + threadIdx.x;
    size_t tot = (size_t)(total_steps + 1) * Hdim;
    if (i < Hdim) d_Hbuf[i] = 0.0f;
    else if (i < tot) ((uint32_t*)d_Hbuf)[i] = POISON;
}

// ---------------- tf32 helpers ----------------
__device__ __forceinline__ uint32_t f2tf32(float x) {
    uint32_t u;
    asm("cvt.rna.tf32.f32 %0, %1;" : "=r"(u) : "f"(x));
    return u;
}

__device__ __forceinline__ void mma_tf32(float d[4], const uint32_t a[4],
                                         const uint32_t b[2]) {
    asm volatile("mma.sync.aligned.m16n8k8.row.col.f32.tf32.tf32.f32 "
                 "{%0,%1,%2,%3}, {%4,%5,%6,%7}, {%8,%9}, {%0,%1,%2,%3};"
                 : "+f"(d[0]), "+f"(d[1]), "+f"(d[2]), "+f"(d[3])
                 : "r"(a[0]), "r"(a[1]), "r"(a[2]), "r"(a[3]),
                   "r"(b[0]), "r"(b[1]));
}

#define OG_STR 36

// ---------------- Xp GEMM (tf32): Xp[t][r] = Wih[r,:].emb[state[t],:] + b[r] ----------------
__global__ __launch_bounds__(256, 2) void xp_gemm_tc(const int* __restrict__ state,
                                                     const float* __restrict__ Wih,
                                                     const float* __restrict__ emb,
                                                     const float* __restrict__ bih,
                                                     const float* __restrict__ bhh,
                                                     int S) {
    __shared__ uint32_t As[128 * OG_STR];
    __shared__ uint32_t Bs[128 * OG_STR];

    int bn = blockIdx.x, bm = blockIdx.y;
    int tid = threadIdx.x;
    int warp = tid >> 5;
    int lane = tid & 31;
    int grp = lane >> 2;
    int tg  = lane & 3;
    int wm = (warp & 1) * 64;
    int wn = (warp >> 1) * 32;

    int lr = tid >> 1;
    int part = (tid & 1) * 16;

    const float* Aptr = Wih + (size_t)(bm * 128 + lr) * Edim + part;
    int nrow = bn * 128 + lr; if (nrow >= S) nrow = S - 1;
    const float* Bptr = emb + (size_t)state[nrow] * Edim + part;

    float d[4][4][4];
#pragma unroll
    for (int i = 0; i < 4; i++)
#pragma unroll
        for (int j = 0; j < 4; j++)
#pragma unroll
            for (int k = 0; k < 4; k++) d[i][j][k] = 0.0f;

    for (int k0 = 0; k0 < Edim; k0 += 32) {
#pragma unroll
        for (int i = 0; i < 4; i++) {
            float4 av = *(const float4*)(Aptr + k0 + i * 4);
            float4 bv = *(const float4*)(Bptr + k0 + i * 4);
            uint32_t* ad = &As[lr * OG_STR + part + i * 4];
            uint32_t* bd = &Bs[lr * OG_STR + part + i * 4];
            ad[0] = f2tf32(av.x); ad[1] = f2tf32(av.y);
            ad[2] = f2tf32(av.z); ad[3] = f2tf32(av.w);
            bd[0] = f2tf32(bv.x); bd[1] = f2tf32(bv.y);
            bd[2] = f2tf32(bv.z); bd[3] = f2tf32(bv.w);
        }
        __syncthreads();

#pragma unroll
        for (int kk = 0; kk < 32; kk += 8) {
            uint32_t fb[4][2];
#pragma unroll
            for (int na = 0; na < 4; na++) {
                int n = wn + na * 8 + grp;
                fb[na][0] = Bs[n * OG_STR + kk + tg];
                fb[na][1] = Bs[n * OG_STR + kk + tg + 4];
            }
            uint32_t fa[4][4];
#pragma unroll
            for (int ma = 0; ma < 4; ma++) {
                int m = wm + ma * 16;
                fa[ma][0] = As[(m + grp) * OG_STR + kk + tg];
                fa[ma][1] = As[(m + 8 + grp) * OG_STR + kk + tg];
                fa[ma][2] = As[(m + grp) * OG_STR + kk + tg + 4];
                fa[ma][3] = As[(m + 8 + grp) * OG_STR + kk + tg + 4];
            }
#pragma unroll
            for (int ma = 0; ma < 4; ma++)
#pragma unroll
                for (int na = 0; na < 4; na++)
                    mma_tf32(d[ma][na], fa[ma], fb[na]);
        }
        __syncthreads();
    }

    // transposed epilogue: Xp[t][r] = d + bias[r]
#pragma unroll
    for (int ma = 0; ma < 4; ma++) {
        int m0 = bm * 128 + wm + ma * 16 + grp;
        float b0 = bih[m0] + bhh[m0];
        float b1 = bih[m0 + 8] + bhh[m0 + 8];
#pragma unroll
        for (int na = 0; na < 4; na++) {
            int n0 = bn * 128 + wn + na * 8 + tg * 2;
            if (n0 < S) {
                float* xr = d_Xp + (size_t)n0 * GATES;
                xr[m0]     = d[ma][na][0] + b0;
                xr[m0 + 8] = d[ma][na][2] + b1;
            }
            if (n0 + 1 < S) {
                float* xr = d_Xp + (size_t)(n0 + 1) * GATES;
                xr[m0]     = d[ma][na][1] + b0;
                xr[m0 + 8] = d[ma][na][3] + b1;
            }
        }
    }
}

// ---------------- persistent recurrence kernel (R10 structure; f32x2 dot) ----------------
__device__ __forceinline__ float sigmoid_f(float x) { return 1.0f / (1.0f + __expf(-x)); }
__device__ __forceinline__ float tanh_f(float x) { return 1.0f - 2.0f / (__expf(2.0f * x) + 1.0f); }

__global__ __launch_bounds__(256, 1) void recur(const float* __restrict__ encWhh,
                                                const float* __restrict__ decWhh,
                                                const float* __restrict__ dbih,
                                                const float* __restrict__ dbhh,
                                                int S, int D) {
    __shared__ float4 hs4[8 * 33];   // padded h (33 float4 per 32-float4 segment)
    __shared__ float  g_s[32];
    __shared__ float  c_s[8];

    int tid = threadIdx.x;
    int b = blockIdx.x;
    int seg = tid & 7;
    int rl = tid >> 3;               // 0..31
    int gate = rl >> 3, q = rl & 7;
    int R = gate * 1024 + b * 8 + q;

    if (tid < 8) c_s[tid] = 0.0f;

    // weights for this lane's 128 columns, as 32 x (2 packed f32x2)
    ulonglong2 w2[32];
    {
        const ulonglong2* src = (const ulonglong2*)(encWhh + (size_t)R * Hdim + seg * 128);
#pragma unroll
        for (int k = 0; k < 32; k++) w2[k] = src[k];
    }
    float decB = 0.0f;
    if (seg == 0) decB = dbih[R] + dbhh[R];

    int TS = S + D;
    for (int t = 0; t < TS; t++) {
        if (t == S) {  // switch to decoder weights
            const ulonglong2* src = (const ulonglong2*)(decWhh + (size_t)R * Hdim + seg * 128);
#pragma unroll
            for (int k = 0; k < 32; k++) w2[k] = src[k];
        }

        // issue per-row additive term load EARLY (DRAM latency overlaps the poll)
        float extra = 0.0f;
        if (seg == 0) extra = (t < S) ? d_Xp[(size_t)t * GATES + R] : decB;

        // data-is-the-flag: spin on OUR 16B of h_t until all 4 lanes non-poison.
        uint32_t x0, x1, x2, x3;
        {
            const uint32_t* hp = (const uint32_t*)(d_Hbuf + (size_t)t * Hdim) + tid * 4;
            do {
                asm volatile("ld.relaxed.gpu.global.v4.u32 {%0,%1,%2,%3}, [%4];"
                             : "=r"(x0), "=r"(x1), "=r"(x2), "=r"(x3) : "l"(hp));
            } while (x0 == POISON || x1 == POISON || x2 == POISON || x3 == POISON);
        }
        {
            float4 hv;
            hv.x = __uint_as_float(x0); hv.y = __uint_as_float(x1);
            hv.z = __uint_as_float(x2); hv.w = __uint_as_float(x3);
            hs4[tid + (tid >> 5)] = hv;
        }
        __syncthreads();

        // 128-wide partial dot: 64 packed fma.f32x2 (= 4 independent scalar chains)
        unsigned long long acc0 = 0ull, acc1 = 0ull;   // each holds (f32,f32) = (0,0)
        {
            const ulonglong2* hp = (const ulonglong2*)&hs4[seg * 33];
#pragma unroll
            for (int k = 0; k < 32; k++) {
                ulonglong2 hv = hp[k];
                asm("fma.rn.f32x2 %0, %1, %2, %0;"
                    : "+l"(acc0) : "l"(w2[k].x), "l"(hv.x));
                asm("fma.rn.f32x2 %0, %1, %2, %0;"
                    : "+l"(acc1) : "l"(w2[k].y), "l"(hv.y));
            }
        }
        float s0, s1, s2, s3;
        asm("mov.b64 {%0,%1}, %2;" : "=f"(s0), "=f"(s1) : "l"(acc0));
        asm("mov.b64 {%0,%1}, %2;" : "=f"(s2), "=f"(s3) : "l"(acc1));
        float acc = (s0 + s1) + (s2 + s3);
        acc += __shfl_xor_sync(0xffffffffu, acc, 1);
        acc += __shfl_xor_sync(0xffffffffu, acc, 2);
        acc += __shfl_xor_sync(0xffffffffu, acc, 4);
        if (seg == 0) g_s[rl] = acc + extra;
        __syncthreads();

        // LSTM cell: 32 lanes compute 4 gate activations in parallel, 8 finish
        if (tid < 32) {
            float gv = g_s[tid];
            float act = ((tid >> 3) == 2) ? tanh_f(gv) : sigmoid_f(gv);
            int qq = tid & 7;
            float a_i = __shfl_sync(0xffffffffu, act, qq);
            float a_f = __shfl_sync(0xffffffffu, act, 8 + qq);
            float a_g = __shfl_sync(0xffffffffu, act, 16 + qq);
            float a_o = __shfl_sync(0xffffffffu, act, 24 + qq);
            if (tid < 8) {
                float c = a_f * c_s[tid] + a_i * a_g;
                c_s[tid] = c;
                float h = a_o * tanh_f(c);
                float* hw = d_Hbuf + (size_t)(t + 1) * Hdim + b * 8 + tid;
                asm volatile("st.relaxed.gpu.global.f32 [%0], %1;"
                             :: "l"(hw), "f"(h) : "memory");
            }
        }
        // no global counter, no fence: next iteration's poll is the sync
    }
}

// ---------------- output GEMM (tf32 tensor cores, R10-exact) ----------------
__global__ __launch_bounds__(256, 2) void out_gemm_tc(const float* __restrict__ Wout,
                                                      const float* __restrict__ bout,
                                                      float* __restrict__ out,
                                                      int hoff, int M, int N) {
    __shared__ uint32_t As[128 * OG_STR];
    __shared__ uint32_t Bs[128 * OG_STR];

    int bn = blockIdx.x, bm = blockIdx.y;
    int tid = threadIdx.x;
    int warp = tid >> 5;
    int lane = tid & 31;
    int grp = lane >> 2;
    int tg  = lane & 3;
    int wm = (warp & 1) * 64;
    int wn = (warp >> 1) * 32;

    int lr = tid >> 1;
    int part = (tid & 1) * 16;

    const float* Aptr = d_Hbuf + (size_t)(hoff + bm * 128 + lr) * Hdim + part;
    int nrow = bn * 128 + lr; if (nrow >= N) nrow = N - 1;
    const float* Bptr = Wout + (size_t)nrow * Hdim + part;

    float d[4][4][4];
#pragma unroll
    for (int i = 0; i < 4; i++)
#pragma unroll
        for (int j = 0; j < 4; j++)
#pragma unroll
            for (int k = 0; k < 4; k++) d[i][j][k] = 0.0f;

    for (int k0 = 0; k0 < Hdim; k0 += 32) {
#pragma unroll
        for (int i = 0; i < 4; i++) {
            float4 av = *(const float4*)(Aptr + k0 + i * 4);
            float4 bv = *(const float4*)(Bptr + k0 + i * 4);
            uint32_t* ad = &As[lr * OG_STR + part + i * 4];
            uint32_t* bd = &Bs[lr * OG_STR + part + i * 4];
            ad[0] = f2tf32(av.x); ad[1] = f2tf32(av.y);
            ad[2] = f2tf32(av.z); ad[3] = f2tf32(av.w);
            bd[0] = f2tf32(bv.x); bd[1] = f2tf32(bv.y);
            bd[2] = f2tf32(bv.z); bd[3] = f2tf32(bv.w);
        }
        __syncthreads();

#pragma unroll
        for (int kk = 0; kk < 32; kk += 8) {
            uint32_t fb[4][2];
#pragma unroll
            for (int na = 0; na < 4; na++) {
                int n = wn + na * 8 + grp;
                fb[na][0] = Bs[n * OG_STR + kk + tg];
                fb[na][1] = Bs[n * OG_STR + kk + tg + 4];
            }
            uint32_t fa[4][4];
#pragma unroll
            for (int ma = 0; ma < 4; ma++) {
                int m = wm + ma * 16;
                fa[ma][0] = As[(m + grp) * OG_STR + kk + tg];
                fa[ma][1] = As[(m + 8 + grp) * OG_STR + kk + tg];
                fa[ma][2] = As[(m + grp) * OG_STR + kk + tg + 4];
                fa[ma][3] = As[(m + 8 + grp) * OG_STR + kk + tg + 4];
            }
#pragma unroll
            for (int ma = 0; ma < 4; ma++)
#pragma unroll
                for (int na = 0; na < 4; na++)
                    mma_tf32(d[ma][na], fa[ma], fb[na]);
        }
        __syncthreads();
    }

    // epilogue: scalar stores (N odd -> rows only 4B aligned)
#pragma unroll
    for (int ma = 0; ma < 4; ma++) {
        int m0 = bm * 128 + wm + ma * 16 + grp;
        float* r0 = out + (size_t)m0 * N;
        float* r1 = out + (size_t)(m0 + 8) * N;
#pragma unroll
        for (int na = 0; na < 4; na++) {
            int n0 = bn * 128 + wn + na * 8 + tg * 2;
            if (n0 < N) {
                float bb = bout[n0];
                r0[n0] = d[ma][na][0] + bb;
                r1[n0] = d[ma][na][2] + bb;
            }
            if (n0 + 1 < N) {
                float bb = bout[n0 + 1];
                r0[n0 + 1] = d[ma][na][1] + bb;
                r1[n0 + 1] = d[ma][na][3] + bb;
            }
        }
    }
}

// ---------------- row softmax (in place, single-exp: store e in pass 2) ----------------
__global__ void softmax_rows(float* __restrict__ out, int N) {
    int row = blockIdx.x;
    float* p = out + (size_t)row * N;
    int tid = threadIdx.x;
    __shared__ float red[256];

    float mx = -1e30f;
    for (int i = tid; i < N; i += 256) mx = fmaxf(mx, p[i]);
    red[tid] = mx; __syncthreads();
    for (int s = 128; s > 0; s >>= 1) {
        if (tid < s) red[tid] = fmaxf(red[tid], red[tid + s]);
        __syncthreads();
    }
    mx = red[0]; __syncthreads();

    // pass 2: compute e once, store it, accumulate sum (halves MUFU work)
    float sum = 0.0f;
    for (int i = tid; i < N; i += 256) {
        float e = __expf(p[i] - mx);
        p[i] = e;
        sum += e;
    }
    red[tid] = sum; __syncthreads();
    for (int s = 128; s > 0; s >>= 1) {
        if (tid < s) red[tid] += red[tid + s];
        __syncthreads();
    }
    float inv = 1.0f / red[0];

    // pass 3: pure scale (no exp)
    for (int i = tid; i < N; i += 256) p[i] *= inv;
}

// ---------------- launch ----------------
extern "C" void kernel_launch(void* const* d_in, const int* in_sizes, int n_in,
                              void* d_out, int out_size) {
    const int*   state   = (const int*)d_in[0];
    const float* emb     = (const float*)d_in[2];
    const float* enc_Wih = (const float*)d_in[3];
    const float* enc_Whh = (const float*)d_in[4];
    const float* enc_bih = (const float*)d_in[5];
    const float* enc_bhh = (const float*)d_in[6];
    const float* dec_Whh = (const float*)d_in[8];
    const float* dec_bih = (const float*)d_in[9];
    const float* dec_bhh = (const float*)d_in[10];
    const float* Wout    = (const float*)d_in[11];
    const float* bout    = (const float*)d_in[12];

    int S = in_sizes[0];                 // encoder sequence length (2048)
    int V = in_sizes[12];                // vocab out (50257)
    int D = out_size / V;                // decoder steps (512)
    int TS = S + D;
    float* out = (float*)d_out;

    size_t initElems = (size_t)(TS + 1) * Hdim;
    init_kernel<<<(int)((initElems + 255) / 256), 256>>>(TS);

    xp_gemm_tc<<<dim3((S + 127) / 128, GATES / 128), 256>>>(state, enc_Wih, emb,
                                                            enc_bih, enc_bhh, S);

    recur<<<G_CTAS, 256>>>(enc_Whh, dec_Whh, dec_bih, dec_bhh, S, D);

    out_gemm_tc<<<dim3((V + 127) / 128, (D + 127) / 128), 256>>>(Wout, bout, out,
                                                                 S + 1, D, V);

    softmax_rows<<<D, 256>>>(out, V);
}

// round 17
// speedup vs baseline: 1.5057x; 1.0043x over previous
#include <cuda_runtime.h>
#include <math.h>
#include <stdint.h>

#define Hdim   1024
#define Edim   512
#define GATES  4096          // 4*Hdim
#define MAXS   2048
#define MAXD   512
#define G_CTAS 128           // Hdim/8 CTAs, all resident (<=148 SMs)
#define POISON 0x7FBFFFFFu   // NaN bit pattern; h=o*tanh(c) can never be NaN

// ---------------- persistent device state ----------------
__device__ __align__(16) float d_Xp[(size_t)MAXS * GATES];               // encoder input projections (+bias)
__device__ __align__(16) float d_Hbuf[(size_t)(MAXS + MAXD + 1) * Hdim]; // h_t for every step (step-indexed)

// ---------------- init: zero h0, poison h1..hTS (data-is-the-flag sync) ----------------
__global__ void init_kernel(int total_steps) {
    size_t i = (size_t)blockIdx.x * blockDim.x + threadIdx.x;
    size_t tot = (size_t)(total_steps + 1) * Hdim;
    if (i < Hdim) d_Hbuf[i] = 0.0f;
    else if (i < tot) ((uint32_t*)d_Hbuf)[i] = POISON;
}

// ---------------- tf32 helpers ----------------
__device__ __forceinline__ uint32_t f2tf32(float x) {
    uint32_t u;
    asm("cvt.rna.tf32.f32 %0, %1;" : "=r"(u) : "f"(x));
    return u;
}

__device__ __forceinline__ void mma_tf32(float d[4], const uint32_t a[4],
                                         const uint32_t b[2]) {
    asm volatile("mma.sync.aligned.m16n8k8.row.col.f32.tf32.tf32.f32 "
                 "{%0,%1,%2,%3}, {%4,%5,%6,%7}, {%8,%9}, {%0,%1,%2,%3};"
                 : "+f"(d[0]), "+f"(d[1]), "+f"(d[2]), "+f"(d[3])
                 : "r"(a[0]), "r"(a[1]), "r"(a[2]), "r"(a[3]),
                   "r"(b[0]), "r"(b[1]));
}

#define OG_STR 36

// ---------------- Xp GEMM (tf32): Xp[t][r] = Wih[r,:].emb[state[t],:] + b[r] ----------------
__global__ __launch_bounds__(256, 2) void xp_gemm_tc(const int* __restrict__ state,
                                                     const float* __restrict__ Wih,
                                                     const float* __restrict__ emb,
                                                     const float* __restrict__ bih,
                                                     const float* __restrict__ bhh,
                                                     int S) {
    __shared__ uint32_t As[128 * OG_STR];
    __shared__ uint32_t Bs[128 * OG_STR];

    int bn = blockIdx.x, bm = blockIdx.y;
    int tid = threadIdx.x;
    int warp = tid >> 5;
    int lane = tid & 31;
    int grp = lane >> 2;
    int tg  = lane & 3;
    int wm = (warp & 1) * 64;
    int wn = (warp >> 1) * 32;

    int lr = tid >> 1;
    int part = (tid & 1) * 16;

    const float* Aptr = Wih + (size_t)(bm * 128 + lr) * Edim + part;
    int nrow = bn * 128 + lr; if (nrow >= S) nrow = S - 1;
    const float* Bptr = emb + (size_t)state[nrow] * Edim + part;

    float d[4][4][4];
#pragma unroll
    for (int i = 0; i < 4; i++)
#pragma unroll
        for (int j = 0; j < 4; j++)
#pragma unroll
            for (int k = 0; k < 4; k++) d[i][j][k] = 0.0f;

    for (int k0 = 0; k0 < Edim; k0 += 32) {
#pragma unroll
        for (int i = 0; i < 4; i++) {
            float4 av = *(const float4*)(Aptr + k0 + i * 4);
            float4 bv = *(const float4*)(Bptr + k0 + i * 4);
            uint32_t* ad = &As[lr * OG_STR + part + i * 4];
            uint32_t* bd = &Bs[lr * OG_STR + part + i * 4];
            ad[0] = f2tf32(av.x); ad[1] = f2tf32(av.y);
            ad[2] = f2tf32(av.z); ad[3] = f2tf32(av.w);
            bd[0] = f2tf32(bv.x); bd[1] = f2tf32(bv.y);
            bd[2] = f2tf32(bv.z); bd[3] = f2tf32(bv.w);
        }
        __syncthreads();

#pragma unroll
        for (int kk = 0; kk < 32; kk += 8) {
            uint32_t fb[4][2];
#pragma unroll
            for (int na = 0; na < 4; na++) {
                int n = wn + na * 8 + grp;
                fb[na][0] = Bs[n * OG_STR + kk + tg];
                fb[na][1] = Bs[n * OG_STR + kk + tg + 4];
            }
            uint32_t fa[4][4];
#pragma unroll
            for (int ma = 0; ma < 4; ma++) {
                int m = wm + ma * 16;
                fa[ma][0] = As[(m + grp) * OG_STR + kk + tg];
                fa[ma][1] = As[(m + 8 + grp) * OG_STR + kk + tg];
                fa[ma][2] = As[(m + grp) * OG_STR + kk + tg + 4];
                fa[ma][3] = As[(m + 8 + grp) * OG_STR + kk + tg + 4];
            }
#pragma unroll
            for (int ma = 0; ma < 4; ma++)
#pragma unroll
                for (int na = 0; na < 4; na++)
                    mma_tf32(d[ma][na], fa[ma], fb[na]);
        }
        __syncthreads();
    }

    // transposed epilogue: Xp[t][r] = d + bias[r]
#pragma unroll
    for (int ma = 0; ma < 4; ma++) {
        int m0 = bm * 128 + wm + ma * 16 + grp;
        float b0 = bih[m0] + bhh[m0];
        float b1 = bih[m0 + 8] + bhh[m0 + 8];
#pragma unroll
        for (int na = 0; na < 4; na++) {
            int n0 = bn * 128 + wn + na * 8 + tg * 2;
            if (n0 < S) {
                float* xr = d_Xp + (size_t)n0 * GATES;
                xr[m0]     = d[ma][na][0] + b0;
                xr[m0 + 8] = d[ma][na][2] + b1;
            }
            if (n0 + 1 < S) {
                float* xr = d_Xp + (size_t)(n0 + 1) * GATES;
                xr[m0]     = d[ma][na][1] + b0;
                xr[m0 + 8] = d[ma][na][3] + b1;
            }
        }
    }
}

// ---------------- persistent recurrence kernel (R15-exact) ----------------
__device__ __forceinline__ float sigmoid_f(float x) { return 1.0f / (1.0f + __expf(-x)); }
__device__ __forceinline__ float tanh_f(float x) { return 1.0f - 2.0f / (__expf(2.0f * x) + 1.0f); }

__global__ __launch_bounds__(256, 1) void recur(const float* __restrict__ encWhh,
                                                const float* __restrict__ decWhh,
                                                const float* __restrict__ dbih,
                                                const float* __restrict__ dbhh,
                                                int S, int D) {
    __shared__ float4 hs4[8 * 33];   // padded h (33 float4 per 32-float4 segment)
    __shared__ float  g_s[32];
    __shared__ float  c_s[8];

    int tid = threadIdx.x;
    int b = blockIdx.x;
    int seg = tid & 7;
    int rl = tid >> 3;               // 0..31
    int gate = rl >> 3, q = rl & 7;
    int R = gate * 1024 + b * 8 + q;

    if (tid < 8) c_s[tid] = 0.0f;

    // weights for this lane's 128 columns, as 32 x (2 packed f32x2)
    ulonglong2 w2[32];
    {
        const ulonglong2* src = (const ulonglong2*)(encWhh + (size_t)R * Hdim + seg * 128);
#pragma unroll
        for (int k = 0; k < 32; k++) w2[k] = src[k];
    }
    float decB = 0.0f;
    if (seg == 0) decB = dbih[R] + dbhh[R];

    int TS = S + D;
    for (int t = 0; t < TS; t++) {
        if (t == S) {  // switch to decoder weights
            const ulonglong2* src = (const ulonglong2*)(decWhh + (size_t)R * Hdim + seg * 128);
#pragma unroll
            for (int k = 0; k < 32; k++) w2[k] = src[k];
        }

        // issue per-row additive term load EARLY (DRAM latency overlaps the poll)
        float extra = 0.0f;
        if (seg == 0) extra = (t < S) ? d_Xp[(size_t)t * GATES + R] : decB;

        // data-is-the-flag: spin on OUR 16B of h_t until all 4 lanes non-poison.
        uint32_t x0, x1, x2, x3;
        {
            const uint32_t* hp = (const uint32_t*)(d_Hbuf + (size_t)t * Hdim) + tid * 4;
            do {
                asm volatile("ld.relaxed.gpu.global.v4.u32 {%0,%1,%2,%3}, [%4];"
                             : "=r"(x0), "=r"(x1), "=r"(x2), "=r"(x3) : "l"(hp));
            } while (x0 == POISON || x1 == POISON || x2 == POISON || x3 == POISON);
        }
        {
            float4 hv;
            hv.x = __uint_as_float(x0); hv.y = __uint_as_float(x1);
            hv.z = __uint_as_float(x2); hv.w = __uint_as_float(x3);
            hs4[tid + (tid >> 5)] = hv;
        }
        __syncthreads();

        // 128-wide partial dot: 64 packed fma.f32x2 (= 4 independent scalar chains)
        unsigned long long acc0 = 0ull, acc1 = 0ull;   // each holds (f32,f32) = (0,0)
        {
            const ulonglong2* hp = (const ulonglong2*)&hs4[seg * 33];
#pragma unroll
            for (int k = 0; k < 32; k++) {
                ulonglong2 hv = hp[k];
                asm("fma.rn.f32x2 %0, %1, %2, %0;"
                    : "+l"(acc0) : "l"(w2[k].x), "l"(hv.x));
                asm("fma.rn.f32x2 %0, %1, %2, %0;"
                    : "+l"(acc1) : "l"(w2[k].y), "l"(hv.y));
            }
        }
        float s0, s1, s2, s3;
        asm("mov.b64 {%0,%1}, %2;" : "=f"(s0), "=f"(s1) : "l"(acc0));
        asm("mov.b64 {%0,%1}, %2;" : "=f"(s2), "=f"(s3) : "l"(acc1));
        float acc = (s0 + s1) + (s2 + s3);
        acc += __shfl_xor_sync(0xffffffffu, acc, 1);
        acc += __shfl_xor_sync(0xffffffffu, acc, 2);
        acc += __shfl_xor_sync(0xffffffffu, acc, 4);
        if (seg == 0) g_s[rl] = acc + extra;
        __syncthreads();

        // LSTM cell: 32 lanes compute 4 gate activations in parallel, 8 finish
        if (tid < 32) {
            float gv = g_s[tid];
            float act = ((tid >> 3) == 2) ? tanh_f(gv) : sigmoid_f(gv);
            int qq = tid & 7;
            float a_i = __shfl_sync(0xffffffffu, act, qq);
            float a_f = __shfl_sync(0xffffffffu, act, 8 + qq);
            float a_g = __shfl_sync(0xffffffffu, act, 16 + qq);
            float a_o = __shfl_sync(0xffffffffu, act, 24 + qq);
            if (tid < 8) {
                float c = a_f * c_s[tid] + a_i * a_g;
                c_s[tid] = c;
                float h = a_o * tanh_f(c);
                float* hw = d_Hbuf + (size_t)(t + 1) * Hdim + b * 8 + tid;
                asm volatile("st.relaxed.gpu.global.f32 [%0], %1;"
                             :: "l"(hw), "f"(h) : "memory");
            }
        }
        // no global counter, no fence: next iteration's poll is the sync
    }
}

// ---------------- output GEMM (tf32 tensor cores) + fused exp epilogue ----------------
// Stores e = exp(logit + bias). Max-free softmax is safe: |logit| <= ||Wrow||*||h||+|b|
// <= 1.6*32+0.3 ~ 52 (|h_i|<1), so exp <= 2e22 and row sum <= 1e27 -- no overflow.
__global__ __launch_bounds__(256, 2) void out_gemm_tc(const float* __restrict__ Wout,
                                                      const float* __restrict__ bout,
                                                      float* __restrict__ out,
                                                      int hoff, int M, int N) {
    __shared__ uint32_t As[128 * OG_STR];
    __shared__ uint32_t Bs[128 * OG_STR];

    int bn = blockIdx.x, bm = blockIdx.y;
    int tid = threadIdx.x;
    int warp = tid >> 5;
    int lane = tid & 31;
    int grp = lane >> 2;
    int tg  = lane & 3;
    int wm = (warp & 1) * 64;
    int wn = (warp >> 1) * 32;

    int lr = tid >> 1;
    int part = (tid & 1) * 16;

    const float* Aptr = d_Hbuf + (size_t)(hoff + bm * 128 + lr) * Hdim + part;
    int nrow = bn * 128 + lr; if (nrow >= N) nrow = N - 1;
    const float* Bptr = Wout + (size_t)nrow * Hdim + part;

    float d[4][4][4];
#pragma unroll
    for (int i = 0; i < 4; i++)
#pragma unroll
        for (int j = 0; j < 4; j++)
#pragma unroll
            for (int k = 0; k < 4; k++) d[i][j][k] = 0.0f;

    for (int k0 = 0; k0 < Hdim; k0 += 32) {
#pragma unroll
        for (int i = 0; i < 4; i++) {
            float4 av = *(const float4*)(Aptr + k0 + i * 4);
            float4 bv = *(const float4*)(Bptr + k0 + i * 4);
            uint32_t* ad = &As[lr * OG_STR + part + i * 4];
            uint32_t* bd = &Bs[lr * OG_STR + part + i * 4];
            ad[0] = f2tf32(av.x); ad[1] = f2tf32(av.y);
            ad[2] = f2tf32(av.z); ad[3] = f2tf32(av.w);
            bd[0] = f2tf32(bv.x); bd[1] = f2tf32(bv.y);
            bd[2] = f2tf32(bv.z); bd[3] = f2tf32(bv.w);
        }
        __syncthreads();

#pragma unroll
        for (int kk = 0; kk < 32; kk += 8) {
            uint32_t fb[4][2];
#pragma unroll
            for (int na = 0; na < 4; na++) {
                int n = wn + na * 8 + grp;
                fb[na][0] = Bs[n * OG_STR + kk + tg];
                fb[na][1] = Bs[n * OG_STR + kk + tg + 4];
            }
            uint32_t fa[4][4];
#pragma unroll
            for (int ma = 0; ma < 4; ma++) {
                int m = wm + ma * 16;
                fa[ma][0] = As[(m + grp) * OG_STR + kk + tg];
                fa[ma][1] = As[(m + 8 + grp) * OG_STR + kk + tg];
                fa[ma][2] = As[(m + grp) * OG_STR + kk + tg + 4];
                fa[ma][3] = As[(m + 8 + grp) * OG_STR + kk + tg + 4];
            }
#pragma unroll
            for (int ma = 0; ma < 4; ma++)
#pragma unroll
                for (int na = 0; na < 4; na++)
                    mma_tf32(d[ma][na], fa[ma], fb[na]);
        }
        __syncthreads();
    }

    // epilogue: store exp(logit + bias); scalar stores (N odd -> rows 4B aligned)
#pragma unroll
    for (int ma = 0; ma < 4; ma++) {
        int m0 = bm * 128 + wm + ma * 16 + grp;
        float* r0 = out + (size_t)m0 * N;
        float* r1 = out + (size_t)(m0 + 8) * N;
#pragma unroll
        for (int na = 0; na < 4; na++) {
            int n0 = bn * 128 + wn + na * 8 + tg * 2;
            if (n0 < N) {
                float bb = bout[n0];
                r0[n0] = __expf(d[ma][na][0] + bb);
                r1[n0] = __expf(d[ma][na][2] + bb);
            }
            if (n0 + 1 < N) {
                float bb = bout[n0 + 1];
                r0[n0 + 1] = __expf(d[ma][na][1] + bb);
                r1[n0 + 1] = __expf(d[ma][na][3] + bb);
            }
        }
    }
}

// ---------------- row normalize (in place): p already holds exp(logit) ----------------
__global__ void softmax_rows(float* __restrict__ out, int N) {
    int row = blockIdx.x;
    float* p = out + (size_t)row * N;
    int tid = threadIdx.x;
    __shared__ float red[256];

    // pass 1: sum of exps (read-only)
    float sum = 0.0f;
    for (int i = tid; i < N; i += 256) sum += p[i];
    red[tid] = sum; __syncthreads();
    for (int s = 128; s > 0; s >>= 1) {
        if (tid < s) red[tid] += red[tid + s];
        __syncthreads();
    }
    float inv = 1.0f / red[0];

    // pass 2: scale
    for (int i = tid; i < N; i += 256) p[i] *= inv;
}

// ---------------- launch ----------------
extern "C" void kernel_launch(void* const* d_in, const int* in_sizes, int n_in,
                              void* d_out, int out_size) {
    const int*   state   = (const int*)d_in[0];
    const float* emb     = (const float*)d_in[2];
    const float* enc_Wih = (const float*)d_in[3];
    const float* enc_Whh = (const float*)d_in[4];
    const float* enc_bih = (const float*)d_in[5];
    const float* enc_bhh = (const float*)d_in[6];
    const float* dec_Whh = (const float*)d_in[8];
    const float* dec_bih = (const float*)d_in[9];
    const float* dec_bhh = (const float*)d_in[10];
    const float* Wout    = (const float*)d_in[11];
    const float* bout    = (const float*)d_in[12];

    int S = in_sizes[0];                 // encoder sequence length (2048)
    int V = in_sizes[12];                // vocab out (50257)
    int D = out_size / V;                // decoder steps (512)
    int TS = S + D;
    float* out = (float*)d_out;

    size_t initElems = (size_t)(TS + 1) * Hdim;
    init_kernel<<<(int)((initElems + 255) / 256), 256>>>(TS);

    xp_gemm_tc<<<dim3((S + 127) / 128, GATES / 128), 256>>>(state, enc_Wih, emb,
                                                            enc_bih, enc_bhh, S);

    recur<<<G_CTAS, 256>>>(enc_Whh, dec_Whh, dec_bih, dec_bhh, S, D);

    out_gemm_tc<<<dim3((V + 127) / 128, (D + 127) / 128), 256>>>(Wout, bout, out,
                                                                 S + 1, D, V);

    softmax_rows<<<D, 256>>>(out, V);
}